// round 10
// baseline (speedup 1.0000x reference)
#include <cuda_runtime.h>
#include <cuda_fp16.h>

#define BS 4
#define NQ 1024
#define NK 1024
#define QD 128
#define VD 128
#define HID 64
#define NP 32                   // half2 h-pairs

#define TQ 8                    // queries per score block
#define TK 128                  // keys per score tile
#define SC_THREADS 256
#define KSH_WORDS (NP * TK)
#define SC_SMEM_BYTES ((3 * KSH_WORDS + NP) * 4)

__device__ unsigned g_qp  [BS * NQ * NP];   // [b][q][p]  half2(q_{2p}, q_{2p+1})
__device__ unsigned g_kp  [BS * NP * NK];   // [b][p][k]  half2(k_{2p}, k_{2p+1})
__device__ __half   g_vhT [BS * VD * NK];   // [b][n][k]  fp16 V transposed
__device__ __half   g_ph  [BS * NQ * NK];   // [b][q][k]  fp16 exp(s), unnormalized
__device__ float    g_sinv[BS * NQ];        // 1/sum per row

__device__ __forceinline__ unsigned tanh2(unsigned x) {
    unsigned y;
    asm("tanh.approx.f16x2 %0, %1;" : "=r"(y) : "r"(x));
    return y;
}

__device__ __forceinline__ void mma16816(float& d0, float& d1, float& d2, float& d3,
                                         unsigned a0, unsigned a1, unsigned a2, unsigned a3,
                                         unsigned b0, unsigned b1) {
    asm("mma.sync.aligned.m16n8k16.row.col.f32.f16.f16.f32 "
        "{%0,%1,%2,%3}, {%4,%5,%6,%7}, {%8,%9}, {%0,%1,%2,%3};"
        : "+f"(d0), "+f"(d1), "+f"(d2), "+f"(d3)
        : "r"(a0), "r"(a1), "r"(a2), "r"(a3), "r"(b0), "r"(b1));
}

__device__ __forceinline__ void cp16(void* dst, const void* src) {
    unsigned d = (unsigned)__cvta_generic_to_shared(dst);
    asm volatile("cp.async.cg.shared.global [%0], [%1], 16;" :: "r"(d), "l"(src));
}
__device__ __forceinline__ void cp_commit() {
    asm volatile("cp.async.commit_group;");
}
template<int N> __device__ __forceinline__ void cp_wait() {
    asm volatile("cp.async.wait_group %0;" :: "n"(N));
}

// ---------------------------------------------------------------------------
// V transpose + fp16:  g_vhT[b][n][k] = (half) values[b][k][n]
// ---------------------------------------------------------------------------
__global__ __launch_bounds__(256) void vt_kernel(const float* __restrict__ values)
{
    __shared__ float tile[32][33];
    int b  = blockIdx.z;
    int k0 = blockIdx.x * 32;
    int n0 = blockIdx.y * 32;
    int t  = threadIdx.x;
    int r  = t >> 5, c = t & 31;

    const float* vb = values + (size_t)b * NK * VD;
    #pragma unroll
    for (int i = 0; i < 4; ++i)
        tile[r + 8 * i][c] = vb[(size_t)(k0 + r + 8 * i) * VD + n0 + c];
    __syncthreads();
    #pragma unroll
    for (int i = 0; i < 4; ++i) {
        int n = n0 + r + 8 * i;
        g_vhT[((size_t)b * VD + n) * NK + k0 + c] = __float2half_rn(tile[c][r + 8 * i]);
    }
}

// ---------------------------------------------------------------------------
// Projection: natural [d][h] W layout (conflict-free), 32 rows/block.
// Thread (h = t&63, rg = t>>6) computes rows rg+4i, i<8.
// ---------------------------------------------------------------------------
#define PJR 32
__global__ __launch_bounds__(256) void proj_kernel(
    const float* __restrict__ queries, const float* __restrict__ keys,
    const float* __restrict__ W_q, const float* __restrict__ W_k)
{
    __shared__ float Ws[QD * HID];      // natural layout, linear copy (32 KB)
    __shared__ float xs[PJR * QD];      // 16 KB

    int bid   = blockIdx.x;
    int which = bid >> 7;               // 0 = q, 1 = k
    int tile  = bid & 127;
    int b     = tile >> 5;
    int r0    = (tile & 31) * PJR;

    const float* X = which ? keys : queries;
    const float* W = which ? W_k  : W_q;
    int t = threadIdx.x;

    for (int i = t; i < QD * HID; i += 256) Ws[i] = W[i];
    const float* xbase = X + ((size_t)b * NQ + r0) * QD;
    for (int i = t; i < PJR * QD; i += 256) xs[i] = xbase[i];
    __syncthreads();

    int h  = t & 63;
    int rg = t >> 6;
    float acc[8] = {0.f, 0.f, 0.f, 0.f, 0.f, 0.f, 0.f, 0.f};
    #pragma unroll 4
    for (int d = 0; d < QD; d += 4) {
        float w0 = Ws[(d + 0) * HID + h];   // conflict-free: bank = h
        float w1 = Ws[(d + 1) * HID + h];
        float w2 = Ws[(d + 2) * HID + h];
        float w3 = Ws[(d + 3) * HID + h];
        #pragma unroll
        for (int i = 0; i < 8; ++i) {
            float4 x4 = *(const float4*)&xs[(rg + 4 * i) * QD + d];  // broadcast
            acc[i] = fmaf(w0, x4.x, fmaf(w1, x4.y,
                     fmaf(w2, x4.z, fmaf(w3, x4.w, acc[i]))));
        }
    }

    int p = h >> 1;
    #pragma unroll
    for (int i = 0; i < 8; ++i) {
        float partner = __shfl_xor_sync(0xffffffffu, acc[i], 1);
        if ((h & 1) == 0) {
            __half2 h2 = __halves2half2(__float2half_rn(acc[i]),
                                        __float2half_rn(partner));
            int r = r0 + rg + 4 * i;
            if (which == 0)
                g_qp[((size_t)b * NQ + r) * NP + p] = *(unsigned*)&h2;
            else
                g_kp[((size_t)b * NP + p) * NK + r] = *(unsigned*)&h2;
        }
    }
}

// ---------------------------------------------------------------------------
// Score kernel: tanh scores -> exp -> fp16 p + 1/sum.
// Triple-buffered cp.async, ONE barrier per tile. 8-pair fp16 chains.
// ---------------------------------------------------------------------------
__global__ __launch_bounds__(SC_THREADS, 4) void score_kernel(
    const float* __restrict__ w_v)
{
    extern __shared__ unsigned scsm[];
    unsigned* ksh = scsm;                   // 3 x [NP][TK]
    unsigned* wp  = scsm + 3 * KSH_WORDS;   // [NP]

    int t    = threadIdx.x;
    int b    = blockIdx.y;
    int q0   = blockIdx.x * TQ;
    int qi   = t >> 5;                      // query row = warp
    int lane = t & 31;

    if (t < NP) {
        __half2 h2 = __halves2half2(__float2half_rn(w_v[2 * t]),
                                    __float2half_rn(w_v[2 * t + 1]));
        wp[t] = *(unsigned*)&h2;
    }

    unsigned qreg[NP];
    {
        const uint4* qp4 = (const uint4*)(g_qp + ((size_t)b * NQ + q0 + qi) * NP);
        #pragma unroll
        for (int g = 0; g < NP / 4; ++g) {
            uint4 v = qp4[g];
            qreg[4 * g + 0] = v.x; qreg[4 * g + 1] = v.y;
            qreg[4 * g + 2] = v.z; qreg[4 * g + 3] = v.w;
        }
    }

    const unsigned* kpb = g_kp + (size_t)b * NP * NK;
    auto stage = [&](int kt) {
        unsigned* dst = ksh + (kt % 3) * KSH_WORDS;
        #pragma unroll
        for (int r = 0; r < 4; ++r) {
            int e4 = t + 256 * r;
            int p = e4 >> 5, k4 = e4 & 31;
            cp16(dst + p * TK + 4 * k4, kpb + (size_t)p * NK + kt * TK + 4 * k4);
        }
    };

    stage(0); cp_commit();
    stage(1); cp_commit();

    __half* prow = g_ph + ((size_t)b * NQ + q0 + qi) * NK;
    const __half2 hzero = __float2half2_rn(0.f);
    float sum = 0.f;

    for (int kt = 0; kt < NK / TK; ++kt) {
        if (kt < 7) cp_wait<1>(); else cp_wait<0>();
        __syncthreads();

        const unsigned* kb = ksh + (kt % 3) * KSH_WORDS;
        float acc[4] = {0.f, 0.f, 0.f, 0.f};
        #pragma unroll
        for (int pg = 0; pg < 4; ++pg) {
            __half2 hacc[4] = {hzero, hzero, hzero, hzero};
            #pragma unroll
            for (int pp = 0; pp < 8; ++pp) {
                int pidx = pg * 8 + pp;
                uint4 kv = *(const uint4*)&kb[pidx * TK + 4 * lane];
                unsigned qw = qreg[pidx];
                __half2 q2 = *(__half2*)&qw;
                unsigned wv = wp[pidx];                 // broadcast LDS
                __half2 w2 = *(__half2*)&wv;
                unsigned kk[4] = {kv.x, kv.y, kv.z, kv.w};
                #pragma unroll
                for (int j = 0; j < 4; ++j) {
                    __half2 s = __hadd2(q2, *(__half2*)&kk[j]);
                    unsigned tt = tanh2(*(unsigned*)&s);
                    hacc[j] = __hfma2(w2, *(__half2*)&tt, hacc[j]);
                }
            }
            #pragma unroll
            for (int j = 0; j < 4; ++j) {
                float2 f = __half22float2(hacc[j]);
                acc[j] += f.x + f.y;
            }
        }

        float e0 = __expf(acc[0]);
        float e1 = __expf(acc[1]);
        float e2 = __expf(acc[2]);
        float e3 = __expf(acc[3]);
        sum += (e0 + e1) + (e2 + e3);
        __half2 p01 = __floats2half2_rn(e0, e1);
        __half2 p23 = __floats2half2_rn(e2, e3);
        uint2 pu;
        pu.x = *(unsigned*)&p01;
        pu.y = *(unsigned*)&p23;
        *(uint2*)(prow + kt * TK + 4 * lane) = pu;

        if (kt < 6) { stage(kt + 2); cp_commit(); }
    }

    #pragma unroll
    for (int o = 16; o > 0; o >>= 1) sum += __shfl_xor_sync(0xffffffffu, sum, o);
    if (lane == 0) g_sinv[b * NQ + q0 + qi] = 1.f / sum;
}

// ---------------------------------------------------------------------------
// PV kernel: out = (P * sinv) @ V via HMMA, cp.async double-buffer.
// Block = 16 queries x 128 cols (grid 64 x BS, 2 blocks/SM).
// ---------------------------------------------------------------------------
#define PVM 16
#define PH_ST 136               // padded halves per P smem row
#define VT_ST 136               // padded halves per V^T smem row
#define PV_PH_HALVES (PVM * PH_ST)
#define PV_VT_HALVES (VD * VT_ST)
#define PV_BUF_HALVES (PV_PH_HALVES + PV_VT_HALVES)
#define PV_SMEM_BYTES (2 * PV_BUF_HALVES * 2)

__global__ __launch_bounds__(256) void pv_kernel(float* __restrict__ out)
{
    extern __shared__ __half pvsm[];

    int t    = threadIdx.x;
    int b    = blockIdx.y;
    int m0   = blockIdx.x * PVM;
    int w    = t >> 5;
    int lane = t & 31;
    int g    = lane >> 2;
    int t4   = lane & 3;
    int cbase = 16 * w;

    const __half* phb = g_ph  + ((size_t)b * NQ + m0) * NK;
    const __half* vTb = g_vhT + (size_t)b * VD * NK;

    auto stage = [&](int ch) {
        __half* buf = pvsm + (ch & 1) * PV_BUF_HALVES;
        __half* phs = buf;
        __half* vss = buf + PV_PH_HALVES;
        int k0 = ch * 128;
        // P chunk [16][128]: 256 x 16B, 1/thread
        {
            int r = t >> 4, j = t & 15;
            cp16(phs + r * PH_ST + 8 * j, phb + (size_t)r * NK + k0 + 8 * j);
        }
        // V^T chunk [128][128]: 2048 x 16B, 8/thread
        #pragma unroll
        for (int i = 0; i < 8; ++i) {
            int e = t + 256 * i;
            int r = e >> 4, j = e & 15;
            cp16(vss + r * VT_ST + 8 * j, vTb + (size_t)r * NK + k0 + 8 * j);
        }
    };

    float c[2][4];
    #pragma unroll
    for (int nt = 0; nt < 2; ++nt)
        #pragma unroll
        for (int i = 0; i < 4; ++i) c[nt][i] = 0.f;

    stage(0); cp_commit();

    for (int ch = 0; ch < 8; ++ch) {
        if (ch < 7) { stage(ch + 1); cp_commit(); }
        if (ch < 7) cp_wait<1>(); else cp_wait<0>();
        __syncthreads();

        const __half* buf  = pvsm + (ch & 1) * PV_BUF_HALVES;
        const __half* ph_s = buf;
        const __half* vst  = buf + PV_PH_HALVES;
        #pragma unroll
        for (int ks = 0; ks < 8; ++ks) {
            int kk = 16 * ks;
            unsigned a0 = *(const unsigned*)(ph_s + (g)     * PH_ST + kk + 2 * t4);
            unsigned a1 = *(const unsigned*)(ph_s + (g + 8) * PH_ST + kk + 2 * t4);
            unsigned a2 = *(const unsigned*)(ph_s + (g)     * PH_ST + kk + 8 + 2 * t4);
            unsigned a3 = *(const unsigned*)(ph_s + (g + 8) * PH_ST + kk + 8 + 2 * t4);
            #pragma unroll
            for (int nt = 0; nt < 2; ++nt) {
                int n = cbase + 8 * nt + g;
                unsigned b0 = *(const unsigned*)(vst + n * VT_ST + kk + 2 * t4);
                unsigned b1 = *(const unsigned*)(vst + n * VT_ST + kk + 8 + 2 * t4);
                mma16816(c[nt][0], c[nt][1], c[nt][2], c[nt][3],
                         a0, a1, a2, a3, b0, b1);
            }
        }
        __syncthreads();
    }

    // Epilogue: normalize, write fp32
    int row0 = m0 + g;
    int row1 = row0 + 8;
    float s0 = g_sinv[b * NQ + row0];
    float s1 = g_sinv[b * NQ + row1];
    float* ob0 = out + ((size_t)b * NQ + row0) * VD;
    float* ob1 = out + ((size_t)b * NQ + row1) * VD;
    #pragma unroll
    for (int nt = 0; nt < 2; ++nt) {
        int col = cbase + 8 * nt + 2 * t4;
        *(float2*)&ob0[col] = make_float2(c[nt][0] * s0, c[nt][1] * s0);
        *(float2*)&ob1[col] = make_float2(c[nt][2] * s1, c[nt][3] * s1);
    }
}

// ---------------------------------------------------------------------------
extern "C" void kernel_launch(void* const* d_in, const int* in_sizes, int n_in,
                              void* d_out, int out_size)
{
    const float* queries = (const float*)d_in[0];
    const float* keys    = (const float*)d_in[1];
    const float* values  = (const float*)d_in[2];
    const float* W_q     = (const float*)d_in[3];
    const float* W_k     = (const float*)d_in[4];
    const float* w_v     = (const float*)d_in[5];
    float* out = (float*)d_out;

    cudaFuncSetAttribute(score_kernel, cudaFuncAttributeMaxDynamicSharedMemorySize,
                         SC_SMEM_BYTES);
    cudaFuncSetAttribute(pv_kernel, cudaFuncAttributeMaxDynamicSharedMemorySize,
                         PV_SMEM_BYTES);

    vt_kernel<<<dim3(NK / 32, VD / 32, BS), 256>>>(values);
    proj_kernel<<<256, 256>>>(queries, keys, W_q, W_k);
    score_kernel<<<dim3(NQ / TQ, BS), SC_THREADS, SC_SMEM_BYTES>>>(w_v);
    pv_kernel<<<dim3(NQ / PVM, BS), 256, PV_SMEM_BYTES>>>(out);
}

// round 11
// speedup vs baseline: 1.0187x; 1.0187x over previous
#include <cuda_runtime.h>
#include <cuda_fp16.h>

#define BS 4
#define NQ 1024
#define NK 1024
#define QD 128
#define VD 128
#define HID 64
#define NP 32                   // half2 h-pairs

#define TQ 8                    // queries per score block
#define TK 128                  // keys per score tile
#define SC_THREADS 256
#define KSH_WORDS (NP * TK)
#define SC_SMEM_BYTES ((3 * KSH_WORDS + NP) * 4)

__device__ unsigned g_qp  [BS * NQ * NP];   // [b][q][p]  half2(q_{2p}, q_{2p+1})
__device__ unsigned g_kp  [BS * NP * NK];   // [b][p][k]  half2(k_{2p}, k_{2p+1})
__device__ __half   g_vhT [BS * VD * NK];   // [b][n][k]  fp16 V transposed
__device__ __half   g_ph  [BS * NQ * NK];   // [b][q][k]  fp16 exp(s), unnormalized
__device__ float    g_sinv[BS * NQ];        // 1/sum per row

__device__ __forceinline__ unsigned tanh2(unsigned x) {
    unsigned y;
    asm("tanh.approx.f16x2 %0, %1;" : "=r"(y) : "r"(x));
    return y;
}

__device__ __forceinline__ void mma16816(float& d0, float& d1, float& d2, float& d3,
                                         unsigned a0, unsigned a1, unsigned a2, unsigned a3,
                                         unsigned b0, unsigned b1) {
    asm("mma.sync.aligned.m16n8k16.row.col.f32.f16.f16.f32 "
        "{%0,%1,%2,%3}, {%4,%5,%6,%7}, {%8,%9}, {%0,%1,%2,%3};"
        : "+f"(d0), "+f"(d1), "+f"(d2), "+f"(d3)
        : "r"(a0), "r"(a1), "r"(a2), "r"(a3), "r"(b0), "r"(b1));
}

__device__ __forceinline__ void cp16(void* dst, const void* src) {
    unsigned d = (unsigned)__cvta_generic_to_shared(dst);
    asm volatile("cp.async.cg.shared.global [%0], [%1], 16;" :: "r"(d), "l"(src));
}
__device__ __forceinline__ void cp_commit() {
    asm volatile("cp.async.commit_group;");
}
template<int N> __device__ __forceinline__ void cp_wait() {
    asm volatile("cp.async.wait_group %0;" :: "n"(N));
}

// ---------------------------------------------------------------------------
// Prep kernel: blocks [0,256) = projections (32 rows/block, natural W layout);
//              blocks [256,768) = V transpose + fp16.
// ---------------------------------------------------------------------------
#define PJR 32
#define PREP_SMEM_BYTES ((QD * HID + PJR * QD) * 4)     // 49152
__global__ __launch_bounds__(256) void prep_kernel(
    const float* __restrict__ queries, const float* __restrict__ keys,
    const float* __restrict__ values,
    const float* __restrict__ W_q, const float* __restrict__ W_k)
{
    extern __shared__ float smp[];
    int bid = blockIdx.x;
    int t   = threadIdx.x;

    if (bid >= 256) {
        // ---- V transpose: g_vhT[b][n][k] = (half) values[b][k][n] ----
        float* tile = smp;                  // [32][33]
        int bid2 = bid - 256;
        int b   = bid2 >> 7;
        int rem = bid2 & 127;
        int k0  = (rem & 31) * 32;
        int n0  = (rem >> 5) * 32;
        int r   = t >> 5, c = t & 31;

        const float* vb = values + (size_t)b * NK * VD;
        #pragma unroll
        for (int i = 0; i < 4; ++i)
            tile[(r + 8 * i) * 33 + c] = vb[(size_t)(k0 + r + 8 * i) * VD + n0 + c];
        __syncthreads();
        #pragma unroll
        for (int i = 0; i < 4; ++i) {
            int n = n0 + r + 8 * i;
            g_vhT[((size_t)b * VD + n) * NK + k0 + c] =
                __float2half_rn(tile[c * 33 + r + 8 * i]);
        }
        return;
    }

    // ---- Projection: natural [d][h] W layout, conflict-free ----
    float* Ws = smp;                        // [QD*HID]
    float* xs = smp + QD * HID;             // [PJR*QD]

    int which = bid >> 7;                   // 0 = q, 1 = k
    int tile  = bid & 127;
    int b     = tile >> 5;
    int r0    = (tile & 31) * PJR;

    const float* X = which ? keys : queries;
    const float* W = which ? W_k  : W_q;

    for (int i = t; i < QD * HID; i += 256) Ws[i] = W[i];
    const float* xbase = X + ((size_t)b * NQ + r0) * QD;
    for (int i = t; i < PJR * QD; i += 256) xs[i] = xbase[i];
    __syncthreads();

    int h  = t & 63;
    int rg = t >> 6;
    float acc[8] = {0.f, 0.f, 0.f, 0.f, 0.f, 0.f, 0.f, 0.f};
    #pragma unroll 4
    for (int d = 0; d < QD; d += 4) {
        float w0 = Ws[(d + 0) * HID + h];
        float w1 = Ws[(d + 1) * HID + h];
        float w2 = Ws[(d + 2) * HID + h];
        float w3 = Ws[(d + 3) * HID + h];
        #pragma unroll
        for (int i = 0; i < 8; ++i) {
            float4 x4 = *(const float4*)&xs[(rg + 4 * i) * QD + d];
            acc[i] = fmaf(w0, x4.x, fmaf(w1, x4.y,
                     fmaf(w2, x4.z, fmaf(w3, x4.w, acc[i]))));
        }
    }

    int p = h >> 1;
    #pragma unroll
    for (int i = 0; i < 8; ++i) {
        float partner = __shfl_xor_sync(0xffffffffu, acc[i], 1);
        if ((h & 1) == 0) {
            __half2 h2 = __halves2half2(__float2half_rn(acc[i]),
                                        __float2half_rn(partner));
            int r = r0 + rg + 4 * i;
            if (which == 0)
                g_qp[((size_t)b * NQ + r) * NP + p] = *(unsigned*)&h2;
            else
                g_kp[((size_t)b * NP + p) * NK + r] = *(unsigned*)&h2;
        }
    }
}

// ---------------------------------------------------------------------------
// Score kernel: tanh scores -> exp -> fp16 p + 1/sum.
// Triple-buffered cp.async, one barrier per tile.
// ---------------------------------------------------------------------------
__global__ __launch_bounds__(SC_THREADS, 4) void score_kernel(
    const float* __restrict__ w_v)
{
    extern __shared__ unsigned scsm[];
    unsigned* ksh = scsm;                   // 3 x [NP][TK]
    unsigned* wp  = scsm + 3 * KSH_WORDS;   // [NP]

    int t    = threadIdx.x;
    int b    = blockIdx.y;
    int q0   = blockIdx.x * TQ;
    int qi   = t >> 5;                      // query row = warp
    int lane = t & 31;

    if (t < NP) {
        __half2 h2 = __halves2half2(__float2half_rn(w_v[2 * t]),
                                    __float2half_rn(w_v[2 * t + 1]));
        wp[t] = *(unsigned*)&h2;
    }

    unsigned qreg[NP];
    {
        const uint4* qp4 = (const uint4*)(g_qp + ((size_t)b * NQ + q0 + qi) * NP);
        #pragma unroll
        for (int g = 0; g < NP / 4; ++g) {
            uint4 v = qp4[g];
            qreg[4 * g + 0] = v.x; qreg[4 * g + 1] = v.y;
            qreg[4 * g + 2] = v.z; qreg[4 * g + 3] = v.w;
        }
    }

    const unsigned* kpb = g_kp + (size_t)b * NP * NK;
    auto stage = [&](int kt) {
        unsigned* dst = ksh + (kt % 3) * KSH_WORDS;
        #pragma unroll
        for (int r = 0; r < 4; ++r) {
            int e4 = t + 256 * r;
            int p = e4 >> 5, k4 = e4 & 31;
            cp16(dst + p * TK + 4 * k4, kpb + (size_t)p * NK + kt * TK + 4 * k4);
        }
    };

    stage(0); cp_commit();
    stage(1); cp_commit();

    __half* prow = g_ph + ((size_t)b * NQ + q0 + qi) * NK;
    const __half2 hzero = __float2half2_rn(0.f);
    float sum = 0.f;

    for (int kt = 0; kt < NK / TK; ++kt) {
        if (kt < 7) cp_wait<1>(); else cp_wait<0>();
        __syncthreads();

        const unsigned* kb = ksh + (kt % 3) * KSH_WORDS;
        float acc[4] = {0.f, 0.f, 0.f, 0.f};
        #pragma unroll
        for (int pg = 0; pg < 4; ++pg) {
            __half2 hacc[4] = {hzero, hzero, hzero, hzero};
            #pragma unroll
            for (int pp = 0; pp < 8; ++pp) {
                int pidx = pg * 8 + pp;
                uint4 kv = *(const uint4*)&kb[pidx * TK + 4 * lane];
                unsigned qw = qreg[pidx];
                __half2 q2 = *(__half2*)&qw;
                unsigned wv = wp[pidx];                 // broadcast LDS
                __half2 w2 = *(__half2*)&wv;
                unsigned kk[4] = {kv.x, kv.y, kv.z, kv.w};
                #pragma unroll
                for (int j = 0; j < 4; ++j) {
                    __half2 s = __hadd2(q2, *(__half2*)&kk[j]);
                    unsigned tt = tanh2(*(unsigned*)&s);
                    hacc[j] = __hfma2(w2, *(__half2*)&tt, hacc[j]);
                }
            }
            #pragma unroll
            for (int j = 0; j < 4; ++j) {
                float2 f = __half22float2(hacc[j]);
                acc[j] += f.x + f.y;
            }
        }

        float e0 = __expf(acc[0]);
        float e1 = __expf(acc[1]);
        float e2 = __expf(acc[2]);
        float e3 = __expf(acc[3]);
        sum += (e0 + e1) + (e2 + e3);
        __half2 p01 = __floats2half2_rn(e0, e1);
        __half2 p23 = __floats2half2_rn(e2, e3);
        uint2 pu;
        pu.x = *(unsigned*)&p01;
        pu.y = *(unsigned*)&p23;
        *(uint2*)(prow + kt * TK + 4 * lane) = pu;

        if (kt < 6) { stage(kt + 2); cp_commit(); }
    }

    #pragma unroll
    for (int o = 16; o > 0; o >>= 1) sum += __shfl_xor_sync(0xffffffffu, sum, o);
    if (lane == 0) g_sinv[b * NQ + q0 + qi] = 1.f / sum;
}

// ---------------------------------------------------------------------------
// PV kernel: out = (P * sinv) @ V via HMMA.
// Block = 32 queries x 128 cols (grid 128). Triple-buffered cp.async,
// one barrier per chunk (stage ch+2 ordered by iter-ch top barrier).
// ---------------------------------------------------------------------------
#define PVM 32
#define PH_ST 136               // padded halves per P smem row
#define VT_ST 136               // padded halves per V^T smem row
#define PV_PH_HALVES (PVM * PH_ST)
#define PV_VT_HALVES (VD * VT_ST)
#define PV_BUF_HALVES (PV_PH_HALVES + PV_VT_HALVES)
#define PV_SMEM_BYTES (3 * PV_BUF_HALVES * 2)

__global__ __launch_bounds__(256) void pv_kernel(float* __restrict__ out)
{
    extern __shared__ __half pvsm[];

    int t    = threadIdx.x;
    int b    = blockIdx.y;
    int m0   = blockIdx.x * PVM;
    int w    = t >> 5;
    int lane = t & 31;
    int g    = lane >> 2;
    int t4   = lane & 3;

    int rbase = (w >= 4) ? 16 : 0;        // warp's m-tile base row (within 32)
    int cbase = 32 * (w & 3);             // warp's 32-col slab

    const __half* phb = g_ph  + ((size_t)b * NQ + m0) * NK;
    const __half* vTb = g_vhT + (size_t)b * VD * NK;

    auto stage = [&](int ch) {
        __half* buf = pvsm + (ch % 3) * PV_BUF_HALVES;
        __half* phs = buf;
        __half* vss = buf + PV_PH_HALVES;
        int k0 = ch * 128;
        // P chunk [32][128]: 512 x 16B, 2/thread
        #pragma unroll
        for (int i = 0; i < 2; ++i) {
            int e = t + 256 * i;
            int r = e >> 4, j = e & 15;
            cp16(phs + r * PH_ST + 8 * j, phb + (size_t)r * NK + k0 + 8 * j);
        }
        // V^T chunk [128][128]: 2048 x 16B, 8/thread
        #pragma unroll
        for (int i = 0; i < 8; ++i) {
            int e = t + 256 * i;
            int r = e >> 4, j = e & 15;
            cp16(vss + r * VT_ST + 8 * j, vTb + (size_t)r * NK + k0 + 8 * j);
        }
    };

    float c[4][4];
    #pragma unroll
    for (int nt = 0; nt < 4; ++nt)
        #pragma unroll
        for (int i = 0; i < 4; ++i) c[nt][i] = 0.f;

    stage(0); cp_commit();
    stage(1); cp_commit();

    for (int ch = 0; ch < 8; ++ch) {
        if (ch < 7) cp_wait<1>(); else cp_wait<0>();
        __syncthreads();

        const __half* buf  = pvsm + (ch % 3) * PV_BUF_HALVES;
        const __half* ph_s = buf;
        const __half* vst  = buf + PV_PH_HALVES;
        #pragma unroll
        for (int ks = 0; ks < 8; ++ks) {
            int kk = 16 * ks;
            unsigned a0 = *(const unsigned*)(ph_s + (rbase + g)     * PH_ST + kk + 2 * t4);
            unsigned a1 = *(const unsigned*)(ph_s + (rbase + g + 8) * PH_ST + kk + 2 * t4);
            unsigned a2 = *(const unsigned*)(ph_s + (rbase + g)     * PH_ST + kk + 8 + 2 * t4);
            unsigned a3 = *(const unsigned*)(ph_s + (rbase + g + 8) * PH_ST + kk + 8 + 2 * t4);
            #pragma unroll
            for (int nt = 0; nt < 4; ++nt) {
                int n = cbase + 8 * nt + g;
                unsigned b0 = *(const unsigned*)(vst + n * VT_ST + kk + 2 * t4);
                unsigned b1 = *(const unsigned*)(vst + n * VT_ST + kk + 8 + 2 * t4);
                mma16816(c[nt][0], c[nt][1], c[nt][2], c[nt][3],
                         a0, a1, a2, a3, b0, b1);
            }
        }

        if (ch < 6) { stage(ch + 2); cp_commit(); }
    }

    // Epilogue: normalize, write fp32
    int row0 = m0 + rbase + g;
    int row1 = row0 + 8;
    float s0 = g_sinv[b * NQ + row0];
    float s1 = g_sinv[b * NQ + row1];
    float* ob0 = out + ((size_t)b * NQ + row0) * VD;
    float* ob1 = out + ((size_t)b * NQ + row1) * VD;
    #pragma unroll
    for (int nt = 0; nt < 4; ++nt) {
        int col = cbase + 8 * nt + 2 * t4;
        *(float2*)&ob0[col] = make_float2(c[nt][0] * s0, c[nt][1] * s0);
        *(float2*)&ob1[col] = make_float2(c[nt][2] * s1, c[nt][3] * s1);
    }
}

// ---------------------------------------------------------------------------
extern "C" void kernel_launch(void* const* d_in, const int* in_sizes, int n_in,
                              void* d_out, int out_size)
{
    const float* queries = (const float*)d_in[0];
    const float* keys    = (const float*)d_in[1];
    const float* values  = (const float*)d_in[2];
    const float* W_q     = (const float*)d_in[3];
    const float* W_k     = (const float*)d_in[4];
    const float* w_v     = (const float*)d_in[5];
    float* out = (float*)d_out;

    cudaFuncSetAttribute(prep_kernel, cudaFuncAttributeMaxDynamicSharedMemorySize,
                         PREP_SMEM_BYTES);
    cudaFuncSetAttribute(score_kernel, cudaFuncAttributeMaxDynamicSharedMemorySize,
                         SC_SMEM_BYTES);
    cudaFuncSetAttribute(pv_kernel, cudaFuncAttributeMaxDynamicSharedMemorySize,
                         PV_SMEM_BYTES);

    prep_kernel<<<768, 256, PREP_SMEM_BYTES>>>(queries, keys, values, W_q, W_k);
    score_kernel<<<dim3(NQ / TQ, BS), SC_THREADS, SC_SMEM_BYTES>>>(w_v);
    pv_kernel<<<dim3(NQ / PVM, BS), 256, PV_SMEM_BYTES>>>(out);
}

// round 12
// speedup vs baseline: 1.0202x; 1.0015x over previous
#include <cuda_runtime.h>
#include <cuda_fp16.h>

#define BS 4
#define NQ 1024
#define NK 1024
#define QD 128
#define VD 128
#define HID 64
#define NP 32                   // half2 h-pairs

#define TQ 8                    // queries per score block
#define TK 128                  // keys per score tile
#define SC_THREADS 256
#define KSH_WORDS (NP * TK)
#define SC_SMEM_BYTES ((3 * KSH_WORDS + NP) * 4)

__device__ unsigned g_qp  [BS * NQ * NP];   // [b][q][p]  half2(q_{2p}, q_{2p+1})
__device__ unsigned g_kp  [BS * NP * NK];   // [b][p][k]  half2(k_{2p}, k_{2p+1})
__device__ __half   g_vhT [BS * VD * NK];   // [b][n][k]  fp16 V transposed
__device__ __half   g_ph  [BS * NQ * NK];   // [b][q][k]  fp16 exp(s), unnormalized
__device__ float    g_sinv[BS * NQ];        // 1/sum per row

__device__ __forceinline__ unsigned tanh2(unsigned x) {
    unsigned y;
    asm("tanh.approx.f16x2 %0, %1;" : "=r"(y) : "r"(x));
    return y;
}

__device__ __forceinline__ void mma16816(float& d0, float& d1, float& d2, float& d3,
                                         unsigned a0, unsigned a1, unsigned a2, unsigned a3,
                                         unsigned b0, unsigned b1) {
    asm("mma.sync.aligned.m16n8k16.row.col.f32.f16.f16.f32 "
        "{%0,%1,%2,%3}, {%4,%5,%6,%7}, {%8,%9}, {%0,%1,%2,%3};"
        : "+f"(d0), "+f"(d1), "+f"(d2), "+f"(d3)
        : "r"(a0), "r"(a1), "r"(a2), "r"(a3), "r"(b0), "r"(b1));
}

__device__ __forceinline__ void cp16(void* dst, const void* src) {
    unsigned d = (unsigned)__cvta_generic_to_shared(dst);
    asm volatile("cp.async.cg.shared.global [%0], [%1], 16;" :: "r"(d), "l"(src));
}
__device__ __forceinline__ void cp_commit() {
    asm volatile("cp.async.commit_group;");
}
template<int N> __device__ __forceinline__ void cp_wait() {
    asm volatile("cp.async.wait_group %0;" :: "n"(N));
}

// ---------------------------------------------------------------------------
// V transpose + fp16:  g_vhT[b][n][k] = (half) values[b][k][n]
// Small static smem (4.3 KB) -> high occupancy, ~4.4 us measured.
// ---------------------------------------------------------------------------
__global__ __launch_bounds__(256) void vt_kernel(const float* __restrict__ values)
{
    __shared__ float tile[32][33];
    int b  = blockIdx.z;
    int k0 = blockIdx.x * 32;
    int n0 = blockIdx.y * 32;
    int t  = threadIdx.x;
    int r  = t >> 5, c = t & 31;

    const float* vb = values + (size_t)b * NK * VD;
    #pragma unroll
    for (int i = 0; i < 4; ++i)
        tile[r + 8 * i][c] = vb[(size_t)(k0 + r + 8 * i) * VD + n0 + c];
    __syncthreads();
    #pragma unroll
    for (int i = 0; i < 4; ++i) {
        int n = n0 + r + 8 * i;
        g_vhT[((size_t)b * VD + n) * NK + k0 + c] = __float2half_rn(tile[c][r + 8 * i]);
    }
}

// ---------------------------------------------------------------------------
// Projection: natural [d][h] W layout (conflict-free), 32 rows/block.
// ---------------------------------------------------------------------------
#define PJR 32
__global__ __launch_bounds__(256) void proj_kernel(
    const float* __restrict__ queries, const float* __restrict__ keys,
    const float* __restrict__ W_q, const float* __restrict__ W_k)
{
    __shared__ float Ws[QD * HID];      // natural layout, linear copy (32 KB)
    __shared__ float xs[PJR * QD];      // 16 KB

    int bid   = blockIdx.x;
    int which = bid >> 7;               // 0 = q, 1 = k
    int tile  = bid & 127;
    int b     = tile >> 5;
    int r0    = (tile & 31) * PJR;

    const float* X = which ? keys : queries;
    const float* W = which ? W_k  : W_q;
    int t = threadIdx.x;

    for (int i = t; i < QD * HID; i += 256) Ws[i] = W[i];
    const float* xbase = X + ((size_t)b * NQ + r0) * QD;
    for (int i = t; i < PJR * QD; i += 256) xs[i] = xbase[i];
    __syncthreads();

    int h  = t & 63;
    int rg = t >> 6;
    float acc[8] = {0.f, 0.f, 0.f, 0.f, 0.f, 0.f, 0.f, 0.f};
    #pragma unroll 4
    for (int d = 0; d < QD; d += 4) {
        float w0 = Ws[(d + 0) * HID + h];   // conflict-free: bank = h
        float w1 = Ws[(d + 1) * HID + h];
        float w2 = Ws[(d + 2) * HID + h];
        float w3 = Ws[(d + 3) * HID + h];
        #pragma unroll
        for (int i = 0; i < 8; ++i) {
            float4 x4 = *(const float4*)&xs[(rg + 4 * i) * QD + d];  // broadcast
            acc[i] = fmaf(w0, x4.x, fmaf(w1, x4.y,
                     fmaf(w2, x4.z, fmaf(w3, x4.w, acc[i]))));
        }
    }

    int p = h >> 1;
    #pragma unroll
    for (int i = 0; i < 8; ++i) {
        float partner = __shfl_xor_sync(0xffffffffu, acc[i], 1);
        if ((h & 1) == 0) {
            __half2 h2 = __halves2half2(__float2half_rn(acc[i]),
                                        __float2half_rn(partner));
            int r = r0 + rg + 4 * i;
            if (which == 0)
                g_qp[((size_t)b * NQ + r) * NP + p] = *(unsigned*)&h2;
            else
                g_kp[((size_t)b * NP + p) * NK + r] = *(unsigned*)&h2;
        }
    }
}

// ---------------------------------------------------------------------------
// Score kernel: tanh scores -> exp -> fp16 p + 1/sum.
// Triple-buffered cp.async, one barrier per tile.
// ---------------------------------------------------------------------------
__global__ __launch_bounds__(SC_THREADS, 4) void score_kernel(
    const float* __restrict__ w_v)
{
    extern __shared__ unsigned scsm[];
    unsigned* ksh = scsm;                   // 3 x [NP][TK]
    unsigned* wp  = scsm + 3 * KSH_WORDS;   // [NP]

    int t    = threadIdx.x;
    int b    = blockIdx.y;
    int q0   = blockIdx.x * TQ;
    int qi   = t >> 5;                      // query row = warp
    int lane = t & 31;

    if (t < NP) {
        __half2 h2 = __halves2half2(__float2half_rn(w_v[2 * t]),
                                    __float2half_rn(w_v[2 * t + 1]));
        wp[t] = *(unsigned*)&h2;
    }

    unsigned qreg[NP];
    {
        const uint4* qp4 = (const uint4*)(g_qp + ((size_t)b * NQ + q0 + qi) * NP);
        #pragma unroll
        for (int g = 0; g < NP / 4; ++g) {
            uint4 v = qp4[g];
            qreg[4 * g + 0] = v.x; qreg[4 * g + 1] = v.y;
            qreg[4 * g + 2] = v.z; qreg[4 * g + 3] = v.w;
        }
    }

    const unsigned* kpb = g_kp + (size_t)b * NP * NK;
    auto stage = [&](int kt) {
        unsigned* dst = ksh + (kt % 3) * KSH_WORDS;
        #pragma unroll
        for (int r = 0; r < 4; ++r) {
            int e4 = t + 256 * r;
            int p = e4 >> 5, k4 = e4 & 31;
            cp16(dst + p * TK + 4 * k4, kpb + (size_t)p * NK + kt * TK + 4 * k4);
        }
    };

    stage(0); cp_commit();
    stage(1); cp_commit();

    __half* prow = g_ph + ((size_t)b * NQ + q0 + qi) * NK;
    const __half2 hzero = __float2half2_rn(0.f);
    float sum = 0.f;

    for (int kt = 0; kt < NK / TK; ++kt) {
        if (kt < 7) cp_wait<1>(); else cp_wait<0>();
        __syncthreads();

        const unsigned* kb = ksh + (kt % 3) * KSH_WORDS;
        float acc[4] = {0.f, 0.f, 0.f, 0.f};
        #pragma unroll
        for (int pg = 0; pg < 4; ++pg) {
            __half2 hacc[4] = {hzero, hzero, hzero, hzero};
            #pragma unroll
            for (int pp = 0; pp < 8; ++pp) {
                int pidx = pg * 8 + pp;
                uint4 kv = *(const uint4*)&kb[pidx * TK + 4 * lane];
                unsigned qw = qreg[pidx];
                __half2 q2 = *(__half2*)&qw;
                unsigned wv = wp[pidx];                 // broadcast LDS
                __half2 w2 = *(__half2*)&wv;
                unsigned kk[4] = {kv.x, kv.y, kv.z, kv.w};
                #pragma unroll
                for (int j = 0; j < 4; ++j) {
                    __half2 s = __hadd2(q2, *(__half2*)&kk[j]);
                    unsigned tt = tanh2(*(unsigned*)&s);
                    hacc[j] = __hfma2(w2, *(__half2*)&tt, hacc[j]);
                }
            }
            #pragma unroll
            for (int j = 0; j < 4; ++j) {
                float2 f = __half22float2(hacc[j]);
                acc[j] += f.x + f.y;
            }
        }

        float e0 = __expf(acc[0]);
        float e1 = __expf(acc[1]);
        float e2 = __expf(acc[2]);
        float e3 = __expf(acc[3]);
        sum += (e0 + e1) + (e2 + e3);
        __half2 p01 = __floats2half2_rn(e0, e1);
        __half2 p23 = __floats2half2_rn(e2, e3);
        uint2 pu;
        pu.x = *(unsigned*)&p01;
        pu.y = *(unsigned*)&p23;
        *(uint2*)(prow + kt * TK + 4 * lane) = pu;

        if (kt < 6) { stage(kt + 2); cp_commit(); }
    }

    #pragma unroll
    for (int o = 16; o > 0; o >>= 1) sum += __shfl_xor_sync(0xffffffffu, sum, o);
    if (lane == 0) g_sinv[b * NQ + q0 + qi] = 1.f / sum;
}

// ---------------------------------------------------------------------------
// PV kernel: out = (P * sinv) @ V via HMMA.
// Block = 32 queries x 128 cols (grid 128). Triple-buffered cp.async,
// one barrier per chunk.
// ---------------------------------------------------------------------------
#define PVM 32
#define PH_ST 136               // padded halves per P smem row
#define VT_ST 136               // padded halves per V^T smem row
#define PV_PH_HALVES (PVM * PH_ST)
#define PV_VT_HALVES (VD * VT_ST)
#define PV_BUF_HALVES (PV_PH_HALVES + PV_VT_HALVES)
#define PV_SMEM_BYTES (3 * PV_BUF_HALVES * 2)

__global__ __launch_bounds__(256) void pv_kernel(float* __restrict__ out)
{
    extern __shared__ __half pvsm[];

    int t    = threadIdx.x;
    int b    = blockIdx.y;
    int m0   = blockIdx.x * PVM;
    int w    = t >> 5;
    int lane = t & 31;
    int g    = lane >> 2;
    int t4   = lane & 3;

    int rbase = (w >= 4) ? 16 : 0;        // warp's m-tile base row (within 32)
    int cbase = 32 * (w & 3);             // warp's 32-col slab

    const __half* phb = g_ph  + ((size_t)b * NQ + m0) * NK;
    const __half* vTb = g_vhT + (size_t)b * VD * NK;

    auto stage = [&](int ch) {
        __half* buf = pvsm + (ch % 3) * PV_BUF_HALVES;
        __half* phs = buf;
        __half* vss = buf + PV_PH_HALVES;
        int k0 = ch * 128;
        #pragma unroll
        for (int i = 0; i < 2; ++i) {
            int e = t + 256 * i;
            int r = e >> 4, j = e & 15;
            cp16(phs + r * PH_ST + 8 * j, phb + (size_t)r * NK + k0 + 8 * j);
        }
        #pragma unroll
        for (int i = 0; i < 8; ++i) {
            int e = t + 256 * i;
            int r = e >> 4, j = e & 15;
            cp16(vss + r * VT_ST + 8 * j, vTb + (size_t)r * NK + k0 + 8 * j);
        }
    };

    float c[4][4];
    #pragma unroll
    for (int nt = 0; nt < 4; ++nt)
        #pragma unroll
        for (int i = 0; i < 4; ++i) c[nt][i] = 0.f;

    stage(0); cp_commit();
    stage(1); cp_commit();

    for (int ch = 0; ch < 8; ++ch) {
        if (ch < 7) cp_wait<1>(); else cp_wait<0>();
        __syncthreads();

        const __half* buf  = pvsm + (ch % 3) * PV_BUF_HALVES;
        const __half* ph_s = buf;
        const __half* vst  = buf + PV_PH_HALVES;
        #pragma unroll
        for (int ks = 0; ks < 8; ++ks) {
            int kk = 16 * ks;
            unsigned a0 = *(const unsigned*)(ph_s + (rbase + g)     * PH_ST + kk + 2 * t4);
            unsigned a1 = *(const unsigned*)(ph_s + (rbase + g + 8) * PH_ST + kk + 2 * t4);
            unsigned a2 = *(const unsigned*)(ph_s + (rbase + g)     * PH_ST + kk + 8 + 2 * t4);
            unsigned a3 = *(const unsigned*)(ph_s + (rbase + g + 8) * PH_ST + kk + 8 + 2 * t4);
            #pragma unroll
            for (int nt = 0; nt < 4; ++nt) {
                int n = cbase + 8 * nt + g;
                unsigned b0 = *(const unsigned*)(vst + n * VT_ST + kk + 2 * t4);
                unsigned b1 = *(const unsigned*)(vst + n * VT_ST + kk + 8 + 2 * t4);
                mma16816(c[nt][0], c[nt][1], c[nt][2], c[nt][3],
                         a0, a1, a2, a3, b0, b1);
            }
        }

        if (ch < 6) { stage(ch + 2); cp_commit(); }
    }

    // Epilogue: normalize, write fp32
    int row0 = m0 + rbase + g;
    int row1 = row0 + 8;
    float s0 = g_sinv[b * NQ + row0];
    float s1 = g_sinv[b * NQ + row1];
    float* ob0 = out + ((size_t)b * NQ + row0) * VD;
    float* ob1 = out + ((size_t)b * NQ + row1) * VD;
    #pragma unroll
    for (int nt = 0; nt < 4; ++nt) {
        int col = cbase + 8 * nt + 2 * t4;
        *(float2*)&ob0[col] = make_float2(c[nt][0] * s0, c[nt][1] * s0);
        *(float2*)&ob1[col] = make_float2(c[nt][2] * s1, c[nt][3] * s1);
    }
}

// ---------------------------------------------------------------------------
extern "C" void kernel_launch(void* const* d_in, const int* in_sizes, int n_in,
                              void* d_out, int out_size)
{
    const float* queries = (const float*)d_in[0];
    const float* keys    = (const float*)d_in[1];
    const float* values  = (const float*)d_in[2];
    const float* W_q     = (const float*)d_in[3];
    const float* W_k     = (const float*)d_in[4];
    const float* w_v     = (const float*)d_in[5];
    float* out = (float*)d_out;

    cudaFuncSetAttribute(score_kernel, cudaFuncAttributeMaxDynamicSharedMemorySize,
                         SC_SMEM_BYTES);
    cudaFuncSetAttribute(pv_kernel, cudaFuncAttributeMaxDynamicSharedMemorySize,
                         PV_SMEM_BYTES);

    vt_kernel<<<dim3(NK / 32, VD / 32, BS), 256>>>(values);
    proj_kernel<<<256, 256>>>(queries, keys, W_q, W_k);
    score_kernel<<<dim3(NQ / TQ, BS), SC_THREADS, SC_SMEM_BYTES>>>(w_v);
    pv_kernel<<<dim3(NQ / PVM, BS), 256, PV_SMEM_BYTES>>>(out);
}